// round 11
// baseline (speedup 1.0000x reference)
#include <cuda_runtime.h>
#include <cstdint>
#include <math.h>

// Problem constants
#define B_  8
#define N_  512
#define HID_ 512
#define H_  8
#define E_  32
#define D_  64
// hidden width of edge MLP = 2*H = 16

// ---------------- scratch (device globals; no runtime allocation) -------------
__device__ float g_q[B_*H_*N_*D_];          // (b,h,n,d)   8 MB
__device__ float g_k[B_*H_*N_*D_];          //             8 MB
__device__ float g_v[B_*H_*N_*D_];          //             8 MB
__device__ float g_att[(size_t)B_*H_*N_*N_];// bias -> probs, (b,h,i,j) 64 MB
__device__ float g_outh[B_*H_*N_*D_];       // attention output per head 8 MB
__device__ int   g_mask_flag;               // 0 = 4-byte words, 1 = packed bytes

// ---------------- helpers ------------------------------------------------------
__device__ __forceinline__ uint32_t f2tf(float f){
  uint32_t u; asm("cvt.rna.tf32.f32 %0, %1;" : "=r"(u) : "f"(f)); return u;
}
// 3xTF32 split: x ~= hi + lo, each representable in tf32
__device__ __forceinline__ void split2(float x, uint32_t& hi, uint32_t& lo){
  asm("cvt.rna.tf32.f32 %0, %1;" : "=r"(hi) : "f"(x));
  float r = x - __uint_as_float(hi);
  asm("cvt.rna.tf32.f32 %0, %1;" : "=r"(lo) : "f"(r));
}
__device__ __forceinline__ void mma8(float c[4],
    uint32_t a0,uint32_t a1,uint32_t a2,uint32_t a3,uint32_t b0,uint32_t b1){
  asm volatile("mma.sync.aligned.m16n8k8.row.col.f32.tf32.tf32.f32 "
    "{%0,%1,%2,%3}, {%4,%5,%6,%7}, {%8,%9}, {%0,%1,%2,%3};\n"
    : "+f"(c[0]),"+f"(c[1]),"+f"(c[2]),"+f"(c[3])
    : "r"(a0),"r"(a1),"r"(a2),"r"(a3),"r"(b0),"r"(b1));
}
// full-precision (3-mma) product accumulate
__device__ __forceinline__ void mma8_3x(float c[4],
    uint32_t a0h,uint32_t a1h,uint32_t a2h,uint32_t a3h,
    uint32_t a0l,uint32_t a1l,uint32_t a2l,uint32_t a3l,
    uint32_t b0h,uint32_t b1h,uint32_t b0l,uint32_t b1l){
  mma8(c, a0h,a1h,a2h,a3h, b0l,b1l);
  mma8(c, a0l,a1l,a2l,a3l, b0h,b1h);
  mma8(c, a0h,a1h,a2h,a3h, b0h,b1h);
}
__device__ __forceinline__ float neginf(){ return __int_as_float(0xff800000u); }

// ---------------- K0: detect mask storage dtype --------------------------------
__global__ void detect_mask_kernel(const uint32_t* __restrict__ pm_words)
{
  __shared__ int found;
  if (threadIdx.x == 0) found = 0;
  __syncthreads();
  for (int i = threadIdx.x; i < 1024; i += blockDim.x) {
    uint32_t w = pm_words[i];
    if (w != 0u && w != 1u && w != 0x3F800000u) found = 1;
  }
  __syncthreads();
  if (threadIdx.x == 0) g_mask_flag = found;
}

// ---------------- K1: QKV projection GEMM (4096x512 @ 512x512), 3xTF32 --------
__global__ __launch_bounds__(256) void proj_kernel(
    const float* __restrict__ x, const float* __restrict__ W,
    const float* __restrict__ bias, const float* __restrict__ ct_key,
    const int* __restrict__ ctype, int sel)
{
  __shared__ float xs[64][33];
  __shared__ float ws[32][65];
  float* out = (sel == 0) ? g_q : (sel == 1) ? g_k : g_v;

  const int t = threadIdx.x, lane = t & 31, warp = t >> 5;
  const int wm = warp & 3, wn = warp >> 2;
  const int row0 = blockIdx.x * 64, col0 = blockIdx.y * 64;
  float acc[4][4] = {};

  for (int kt = 0; kt < 512; kt += 32) {
    { // stage x tile 64x32 (fp32)
      int r = t >> 2, cs = (t & 3) * 8;
      const float4* p = reinterpret_cast<const float4*>(&x[(size_t)(row0 + r) * 512 + kt + cs]);
      float4 v0 = p[0], v1 = p[1];
      xs[r][cs+0]=v0.x; xs[r][cs+1]=v0.y; xs[r][cs+2]=v0.z; xs[r][cs+3]=v0.w;
      xs[r][cs+4]=v1.x; xs[r][cs+5]=v1.y; xs[r][cs+6]=v1.z; xs[r][cs+7]=v1.w;
    }
    { // stage W tile 32x64 (fp32)
      int r = t >> 3, cs = (t & 7) * 8;
      const float4* p = reinterpret_cast<const float4*>(&W[(size_t)(kt + r) * 512 + col0 + cs]);
      float4 v0 = p[0], v1 = p[1];
      ws[r][cs+0]=v0.x; ws[r][cs+1]=v0.y; ws[r][cs+2]=v0.z; ws[r][cs+3]=v0.w;
      ws[r][cs+4]=v1.x; ws[r][cs+5]=v1.y; ws[r][cs+6]=v1.z; ws[r][cs+7]=v1.w;
    }
    __syncthreads();
    #pragma unroll
    for (int kk = 0; kk < 4; kk++) {
      int ar = wm * 16 + (lane >> 2), ac = kk * 8 + (lane & 3);
      uint32_t a0h,a0l,a1h,a1l,a2h,a2l,a3h,a3l;
      split2(xs[ar][ac],   a0h,a0l); split2(xs[ar+8][ac],   a1h,a1l);
      split2(xs[ar][ac+4], a2h,a2l); split2(xs[ar+8][ac+4], a3h,a3l);
      #pragma unroll
      for (int nt = 0; nt < 4; nt++) {
        int bc = wn * 32 + nt * 8 + (lane >> 2);
        uint32_t b0h,b0l,b1h,b1l;
        split2(ws[kk*8 + (lane&3)][bc],     b0h,b0l);
        split2(ws[kk*8 + 4 + (lane&3)][bc], b1h,b1l);
        mma8_3x(acc[nt], a0h,a1h,a2h,a3h, a0l,a1l,a2l,a3l, b0h,b1h,b0l,b1l);
      }
    }
    __syncthreads();
  }

  #pragma unroll
  for (int nt = 0; nt < 4; nt++) {
    #pragma unroll
    for (int q = 0; q < 4; q++) {
      int row = row0 + wm * 16 + (lane >> 2) + ((q >> 1) << 3);
      int col = col0 + wn * 32 + nt * 8 + 2 * (lane & 3) + (q & 1);
      int bidx = row >> 9, n = row & 511, h = col >> 6, d = col & 63;
      float v = acc[nt][q] + bias[col];
      if (sel == 1) v += ct_key[(size_t)ctype[bidx] * 512 + col];
      out[(((size_t)bidx * H_ + h) * N_ + n) * D_ + d] = v;
    }
  }
}

// ---------------- K2: edge MLP (32 -> 16 -> 8) + ct bias + masks --------------
// CORRECTED SHAPES: We1 (32,16), be1 (16), We2 (16,8), be2 (8).
// One block = (b, i, 64 j's).
__global__ __launch_bounds__(128) void edge_kernel(
    const float* __restrict__ ef, const float* __restrict__ We1,
    const float* __restrict__ be1, const float* __restrict__ We2,
    const float* __restrict__ be2, const float* __restrict__ ct_bias,
    const int* __restrict__ ctype, const void* __restrict__ bm_raw,
    const void* __restrict__ pm_raw)
{
  __shared__ float efs[64][33];   // ef tile (j, e)
  __shared__ float h1s[64][17];   // hidden layer (j, c) fp32, c in [0,16)
  __shared__ float ws1[32][17];   // We1 (e, c)
  __shared__ float ws2[16][9];    // We2 (c, h)

  const int t = threadIdx.x, lane = t & 31, warp = t >> 5;
  const int lin = blockIdx.x;
  const int jt = lin & 7, i = (lin >> 3) & 511, b = lin >> 12;
  const int j0 = jt * 64;

  const int mbyte = g_mask_flag;
  const uint32_t*      bm32 = (const uint32_t*)bm_raw;
  const unsigned char* bm8  = (const unsigned char*)bm_raw;
  const uint32_t*      pm32 = (const uint32_t*)pm_raw;
  const unsigned char* pm8  = (const unsigned char*)pm_raw;

  { // ef tile: 64 j x 32 e contiguous = 512 float4
    const float4* p = reinterpret_cast<const float4*>(&ef[(((size_t)b * 512 + i) * 512 + j0) * 32]);
    #pragma unroll
    for (int rep = 0; rep < 4; rep++) {
      int l4 = rep * 128 + t;
      float4 v = p[l4];
      int j = l4 >> 3, c = (l4 & 7) * 4;
      efs[j][c]=v.x; efs[j][c+1]=v.y; efs[j][c+2]=v.z; efs[j][c+3]=v.w;
    }
  }
  { // We1: 512 floats = 128 x float4; row = l/16, col = l%16
    int l = t * 4;
    float4 v = *reinterpret_cast<const float4*>(&We1[l]);
    int r = l >> 4, c = l & 15;
    ws1[r][c]=v.x; ws1[r][c+1]=v.y; ws1[r][c+2]=v.z; ws1[r][c+3]=v.w;
  }
  if (t < 32) { // We2: 128 floats = 32 x float4; row = l/8, col = l%8
    int l = t * 4;
    float4 v = *reinterpret_cast<const float4*>(&We2[l]);
    int r = l >> 3, c = l & 7;
    ws2[r][c]=v.x; ws2[r][c+1]=v.y; ws2[r][c+2]=v.z; ws2[r][c+3]=v.w;
  }
  __syncthreads();

  // layer 1: (64x32)@(32x16). warp owns 16 rows x 16 cols (2 n-tiles)
  float acc1[2][4] = {};
  #pragma unroll
  for (int kk = 0; kk < 4; kk++) {
    int ar = warp * 16 + (lane >> 2), ac = kk * 8 + (lane & 3);
    uint32_t a0 = f2tf(efs[ar][ac]),   a1 = f2tf(efs[ar+8][ac]);
    uint32_t a2 = f2tf(efs[ar][ac+4]), a3 = f2tf(efs[ar+8][ac+4]);
    #pragma unroll
    for (int nt = 0; nt < 2; nt++) {
      uint32_t b0 = f2tf(ws1[kk*8 + (lane&3)][nt*8 + (lane>>2)]);
      uint32_t b1 = f2tf(ws1[kk*8 + 4 + (lane&3)][nt*8 + (lane>>2)]);
      mma8(acc1[nt], a0, a1, a2, a3, b0, b1);
    }
  }

  // elu -> h1s (full fp32)
  #pragma unroll
  for (int nt = 0; nt < 2; nt++)
    #pragma unroll
    for (int q = 0; q < 4; q++) {
      int row = warp * 16 + (lane >> 2) + ((q >> 1) << 3);
      int col = nt * 8 + 2 * (lane & 3) + (q & 1);
      float v = acc1[nt][q] + be1[col];
      h1s[row][col] = (v > 0.f) ? v : expm1f(v);
    }
  __syncthreads();

  // layer 2: (64x16)@(16x8), two k8 steps
  float acc2[4] = {};
  #pragma unroll
  for (int kk = 0; kk < 2; kk++) {
    int ar = warp * 16 + (lane >> 2), ac = kk * 8 + (lane & 3);
    uint32_t a0 = f2tf(h1s[ar][ac]),   a1 = f2tf(h1s[ar+8][ac]);
    uint32_t a2 = f2tf(h1s[ar][ac+4]), a3 = f2tf(h1s[ar+8][ac+4]);
    uint32_t b0 = f2tf(ws2[kk*8 + (lane&3)][lane>>2]);
    uint32_t b1 = f2tf(ws2[kk*8 + 4 + (lane&3)][lane>>2]);
    mma8(acc2, a0, a1, a2, a3, b0, b1);
  }

  const int ct = ctype[b];
  const bool pad_i = mbyte ? (pm8[b * 512 + i] != 0) : (pm32[b * 512 + i] != 0u);
  #pragma unroll
  for (int q = 0; q < 4; q++) {
    int row = warp * 16 + (lane >> 2) + ((q >> 1) << 3);
    int h = 2 * (lane & 3) + (q & 1);
    int j = j0 + row;
    size_t bij = ((size_t)b * 512 + i) * 512 + j;
    bool masked;
    if (mbyte)
      masked = pad_i || (bm8[bij] != 0) || (pm8[b * 512 + j] != 0);
    else
      masked = pad_i || (bm32[bij] != 0u) || (pm32[b * 512 + j] != 0u);
    float v = masked ? neginf() : (acc2[q] + be2[h] + ct_bias[ct * 8 + h]);
    g_att[(((size_t)b * H_ + h) * N_ + i) * N_ + j] = v;
  }
}

// ---------------- K3: attention: S=QK^T/8 + bias, softmax, P@V (3xTF32) -------
__global__ __launch_bounds__(128) void attn_kernel()
{
  __shared__ float S[16][513];
  __shared__ float Qs[16][65];
  __shared__ float KVs[32][65];
  __shared__ float rmax[16], rinv[16];

  const int t = threadIdx.x, lane = t & 31, warp = t >> 5;
  const int bh = blockIdx.x;
  const int i0 = blockIdx.y * 16;

  const float* qb = g_q + (size_t)bh * N_ * D_;
  const float* kb = g_k + (size_t)bh * N_ * D_;
  const float* vb = g_v + (size_t)bh * N_ * D_;
  float* attb = g_att + (size_t)bh * N_ * N_;

  #pragma unroll
  for (int rep = 0; rep < 2; rep++) { // Q tile 16x64
    int l4 = rep * 128 + t;
    int r = l4 >> 4, c = (l4 & 15) * 4;
    float4 v = *reinterpret_cast<const float4*>(&qb[(size_t)(i0 + r) * 64 + c]);
    Qs[r][c]=v.x; Qs[r][c+1]=v.y; Qs[r][c+2]=v.z; Qs[r][c+3]=v.w;
  }

  // ---- S phase: 16 j-tiles of 32; warp owns 8 cols per tile ----
  for (int jt = 0; jt < 16; jt++) {
    __syncthreads();
    #pragma unroll
    for (int rep = 0; rep < 4; rep++) { // K tile 32x64
      int l4 = rep * 128 + t;
      int r = l4 >> 4, c = (l4 & 15) * 4;
      float4 v = *reinterpret_cast<const float4*>(&kb[(size_t)(jt * 32 + r) * 64 + c]);
      KVs[r][c]=v.x; KVs[r][c+1]=v.y; KVs[r][c+2]=v.z; KVs[r][c+3]=v.w;
    }
    __syncthreads();
    float sacc[4] = {};
    #pragma unroll
    for (int kk = 0; kk < 8; kk++) {
      int ar = lane >> 2, ac = kk * 8 + (lane & 3);
      uint32_t a0h,a0l,a1h,a1l,a2h,a2l,a3h,a3l;
      split2(Qs[ar][ac],   a0h,a0l); split2(Qs[ar+8][ac],   a1h,a1l);
      split2(Qs[ar][ac+4], a2h,a2l); split2(Qs[ar+8][ac+4], a3h,a3l);
      int br = warp * 8 + (lane >> 2);
      uint32_t b0h,b0l,b1h,b1l;
      split2(KVs[br][ac],   b0h,b0l);
      split2(KVs[br][ac+4], b1h,b1l);
      mma8_3x(sacc, a0h,a1h,a2h,a3h, a0l,a1l,a2l,a3l, b0h,b1h,b0l,b1l);
    }
    #pragma unroll
    for (int q = 0; q < 4; q++) {
      int r = (lane >> 2) + ((q >> 1) << 3);
      int j = jt * 32 + warp * 8 + 2 * (lane & 3) + (q & 1);
      S[r][j] = sacc[q] * 0.125f + attb[(size_t)(i0 + r) * 512 + j];
    }
  }
  __syncthreads();

  // ---- softmax stats: 8 threads per row ----
  {
    int r = t >> 3, sub = t & 7;
    float m = neginf();
    for (int j = sub; j < 512; j += 8) m = fmaxf(m, S[r][j]);
    #pragma unroll
    for (int o = 4; o; o >>= 1) m = fmaxf(m, __shfl_xor_sync(0xffffffffu, m, o));
    float s = 0.f;
    if (m != neginf())
      for (int j = sub; j < 512; j += 8) s += expf(S[r][j] - m);
    #pragma unroll
    for (int o = 4; o; o >>= 1) s += __shfl_xor_sync(0xffffffffu, s, o);
    if (sub == 0) { rmax[r] = m; rinv[r] = (m == neginf() || s == 0.f) ? 0.f : 1.f / s; }
  }
  __syncthreads();

  // ---- normalize, write probs (coalesced), keep probs in S ----
  for (int idx = t; idx < 16 * 512; idx += 128) {
    int r = idx >> 9, j = idx & 511;
    float inv = rinv[r];
    float p = (inv == 0.f) ? 0.f : expf(S[r][j] - rmax[r]) * inv;
    S[r][j] = p;
    attb[(size_t)(i0 + r) * 512 + j] = p;
  }

  // ---- AV phase: out(16x64) = P(16x512) @ V(512x64); warp owns 16 d-cols ----
  float oacc[2][4] = {};
  for (int jt = 0; jt < 16; jt++) {
    __syncthreads();
    #pragma unroll
    for (int rep = 0; rep < 4; rep++) { // V tile 32x64
      int l4 = rep * 128 + t;
      int r = l4 >> 4, c = (l4 & 15) * 4;
      float4 v = *reinterpret_cast<const float4*>(&vb[(size_t)(jt * 32 + r) * 64 + c]);
      KVs[r][c]=v.x; KVs[r][c+1]=v.y; KVs[r][c+2]=v.z; KVs[r][c+3]=v.w;
    }
    __syncthreads();
    #pragma unroll
    for (int kk = 0; kk < 4; kk++) {
      int ar = lane >> 2, ac = jt * 32 + kk * 8 + (lane & 3);
      uint32_t a0h,a0l,a1h,a1l,a2h,a2l,a3h,a3l;
      split2(S[ar][ac],   a0h,a0l); split2(S[ar+8][ac],   a1h,a1l);
      split2(S[ar][ac+4], a2h,a2l); split2(S[ar+8][ac+4], a3h,a3l);
      #pragma unroll
      for (int nt = 0; nt < 2; nt++) {
        int bc = warp * 16 + nt * 8 + (lane >> 2);
        uint32_t b0h,b0l,b1h,b1l;
        split2(KVs[kk*8 + (lane&3)][bc],     b0h,b0l);
        split2(KVs[kk*8 + 4 + (lane&3)][bc], b1h,b1l);
        mma8_3x(oacc[nt], a0h,a1h,a2h,a3h, a0l,a1l,a2l,a3l, b0h,b1h,b0l,b1l);
      }
    }
  }
  float* ob = g_outh + (size_t)bh * N_ * D_;
  #pragma unroll
  for (int nt = 0; nt < 2; nt++)
    #pragma unroll
    for (int q = 0; q < 4; q++) {
      int r = (lane >> 2) + ((q >> 1) << 3);
      int d = warp * 16 + nt * 8 + 2 * (lane & 3) + (q & 1);
      ob[(size_t)(i0 + r) * 64 + d] = oacc[nt][q];
    }
}

// ---------------- K4: head mean of probs ---------------------------------------
__global__ __launch_bounds__(256) void mean_kernel(float* __restrict__ outm)
{
  int idx = blockIdx.x * 256 + threadIdx.x;
  int b = idx >> 18;
  int ij = idx & 262143;
  const float* base = g_att + (size_t)b * H_ * 262144 + ij;
  float s = 0.f;
  #pragma unroll
  for (int h = 0; h < 8; h++) s += base[(size_t)h * 262144];
  outm[idx] = s * 0.125f;
}

// ---------------- K5: output projection (gathers heads), 3xTF32 ---------------
__global__ __launch_bounds__(256) void outproj_kernel(
    const float* __restrict__ Wo, const float* __restrict__ bo,
    float* __restrict__ out)
{
  __shared__ float xs[64][33];
  __shared__ float ws[32][65];
  const int t = threadIdx.x, lane = t & 31, warp = t >> 5;
  const int wm = warp & 3, wn = warp >> 2;
  const int row0 = blockIdx.x * 64, col0 = blockIdx.y * 64;
  float acc[4][4] = {};

  for (int kt = 0; kt < 512; kt += 32) {
    { // A tile from g_outh (b,h,n,d) gathered as (row=(b,n), col=h*64+d)
      int r = t >> 2, cs = (t & 3) * 8;
      int row = row0 + r, b = row >> 9, n = row & 511;
      int col = kt + cs, h = col >> 6, d = col & 63;
      const float4* p = reinterpret_cast<const float4*>(
          &g_outh[(((size_t)b * H_ + h) * N_ + n) * D_ + d]);
      float4 v0 = p[0], v1 = p[1];
      xs[r][cs+0]=v0.x; xs[r][cs+1]=v0.y; xs[r][cs+2]=v0.z; xs[r][cs+3]=v0.w;
      xs[r][cs+4]=v1.x; xs[r][cs+5]=v1.y; xs[r][cs+6]=v1.z; xs[r][cs+7]=v1.w;
    }
    {
      int r = t >> 3, cs = (t & 7) * 8;
      const float4* p = reinterpret_cast<const float4*>(&Wo[(size_t)(kt + r) * 512 + col0 + cs]);
      float4 v0 = p[0], v1 = p[1];
      ws[r][cs+0]=v0.x; ws[r][cs+1]=v0.y; ws[r][cs+2]=v0.z; ws[r][cs+3]=v0.w;
      ws[r][cs+4]=v1.x; ws[r][cs+5]=v1.y; ws[r][cs+6]=v1.z; ws[r][cs+7]=v1.w;
    }
    __syncthreads();
    #pragma unroll
    for (int kk = 0; kk < 4; kk++) {
      int ar = wm * 16 + (lane >> 2), ac = kk * 8 + (lane & 3);
      uint32_t a0h,a0l,a1h,a1l,a2h,a2l,a3h,a3l;
      split2(xs[ar][ac],   a0h,a0l); split2(xs[ar+8][ac],   a1h,a1l);
      split2(xs[ar][ac+4], a2h,a2l); split2(xs[ar+8][ac+4], a3h,a3l);
      #pragma unroll
      for (int nt = 0; nt < 4; nt++) {
        int bc = wn * 32 + nt * 8 + (lane >> 2);
        uint32_t b0h,b0l,b1h,b1l;
        split2(ws[kk*8 + (lane&3)][bc],     b0h,b0l);
        split2(ws[kk*8 + 4 + (lane&3)][bc], b1h,b1l);
        mma8_3x(acc[nt], a0h,a1h,a2h,a3h, a0l,a1l,a2l,a3l, b0h,b1h,b0l,b1l);
      }
    }
    __syncthreads();
  }
  #pragma unroll
  for (int nt = 0; nt < 4; nt++)
    #pragma unroll
    for (int q = 0; q < 4; q++) {
      int row = row0 + wm * 16 + (lane >> 2) + ((q >> 1) << 3);
      int col = col0 + wn * 32 + nt * 8 + 2 * (lane & 3) + (q & 1);
      out[(size_t)row * 512 + col] = acc[nt][q] + bo[col];
    }
}

// ---------------- launch --------------------------------------------------------
// Positional dict-order inputs (confirmed by R10's error-delta analysis).
// Corrected tail shapes: We1 (32,16)=512, be1 16, We2 (16,8)=128, be2 8.
extern "C" void kernel_launch(void* const* d_in, const int* in_sizes, int n_in,
                              void* d_out, int out_size)
{
  (void)in_sizes; (void)n_in; (void)out_size;
  const float* x   = (const float*)d_in[0];
  const int*   ct  = (const int*)d_in[1];
  const float* ef  = (const float*)d_in[2];
  const void*  bm  = d_in[3];
  const void*  pm  = d_in[4];
  const float* Wq  = (const float*)d_in[5];  const float* bq  = (const float*)d_in[6];
  const float* Wk  = (const float*)d_in[7];  const float* bk  = (const float*)d_in[8];
  const float* Wv  = (const float*)d_in[9];  const float* bv  = (const float*)d_in[10];
  const float* Wo  = (const float*)d_in[11]; const float* bo  = (const float*)d_in[12];
  const float* We1 = (const float*)d_in[13]; const float* be1 = (const float*)d_in[14];
  const float* We2 = (const float*)d_in[15]; const float* be2 = (const float*)d_in[16];
  const float* ctk = (const float*)d_in[17]; const float* ctb = (const float*)d_in[18];
  float* out = (float*)d_out;

  detect_mask_kernel<<<1, 256>>>((const uint32_t*)pm);

  dim3 gproj(64, 8);
  proj_kernel<<<gproj, 256>>>(x, Wq, bq, ctk, ct, 0);
  proj_kernel<<<gproj, 256>>>(x, Wk, bk, ctk, ct, 1);
  proj_kernel<<<gproj, 256>>>(x, Wv, bv, ctk, ct, 2);

  edge_kernel<<<B_ * N_ * (N_ / 64), 128>>>(ef, We1, be1, We2, be2, ctb, ct, bm, pm);

  attn_kernel<<<dim3(B_ * H_, N_ / 16), 128>>>();

  mean_kernel<<<(B_ * N_ * N_) / 256, 256>>>(out + (size_t)B_ * N_ * HID_);

  outproj_kernel<<<gproj, 256>>>(Wo, bo, out);
}

// round 12
// speedup vs baseline: 1.0524x; 1.0524x over previous
#include <cuda_runtime.h>
#include <cstdint>
#include <math.h>

// Problem constants
#define B_  8
#define N_  512
#define HID_ 512
#define H_  8
#define E_  32
#define D_  64
// hidden width of edge MLP = 2*H = 16

// ---------------- scratch (device globals; no runtime allocation) -------------
__device__ float g_q[B_*H_*N_*D_];          // (b,h,n,d) tf32-rounded  8 MB
__device__ float g_k[B_*H_*N_*D_];          // tf32-rounded            8 MB
__device__ float g_v[B_*H_*N_*D_];          // full fp32               8 MB
__device__ float g_att[(size_t)B_*H_*N_*N_];// bias -> probs, (b,h,i,j) 64 MB
__device__ float g_outh[B_*H_*N_*D_];       // attention output per head 8 MB
__device__ int   g_mask_flag;               // 0 = 4-byte words, 1 = packed bytes

// ---------------- helpers ------------------------------------------------------
__device__ __forceinline__ uint32_t f2tf(float f){
  uint32_t u; asm("cvt.rna.tf32.f32 %0, %1;" : "=r"(u) : "f"(f)); return u;
}
__device__ __forceinline__ void split2(float x, uint32_t& hi, uint32_t& lo){
  asm("cvt.rna.tf32.f32 %0, %1;" : "=r"(hi) : "f"(x));
  float r = x - __uint_as_float(hi);
  asm("cvt.rna.tf32.f32 %0, %1;" : "=r"(lo) : "f"(r));
}
__device__ __forceinline__ void mma8(float c[4],
    uint32_t a0,uint32_t a1,uint32_t a2,uint32_t a3,uint32_t b0,uint32_t b1){
  asm volatile("mma.sync.aligned.m16n8k8.row.col.f32.tf32.tf32.f32 "
    "{%0,%1,%2,%3}, {%4,%5,%6,%7}, {%8,%9}, {%0,%1,%2,%3};\n"
    : "+f"(c[0]),"+f"(c[1]),"+f"(c[2]),"+f"(c[3])
    : "r"(a0),"r"(a1),"r"(a2),"r"(a3),"r"(b0),"r"(b1));
}
__device__ __forceinline__ void mma8_3x(float c[4],
    uint32_t a0h,uint32_t a1h,uint32_t a2h,uint32_t a3h,
    uint32_t a0l,uint32_t a1l,uint32_t a2l,uint32_t a3l,
    uint32_t b0h,uint32_t b1h,uint32_t b0l,uint32_t b1l){
  mma8(c, a0h,a1h,a2h,a3h, b0l,b1l);
  mma8(c, a0l,a1l,a2l,a3l, b0h,b1h);
  mma8(c, a0h,a1h,a2h,a3h, b0h,b1h);
}
__device__ __forceinline__ float neginf(){ return __int_as_float(0xff800000u); }

// ---------------- K0: detect mask storage dtype --------------------------------
__global__ void detect_mask_kernel(const uint32_t* __restrict__ pm_words)
{
  __shared__ int found;
  if (threadIdx.x == 0) found = 0;
  __syncthreads();
  for (int i = threadIdx.x; i < 1024; i += blockDim.x) {
    uint32_t w = pm_words[i];
    if (w != 0u && w != 1u && w != 0x3F800000u) found = 1;
  }
  __syncthreads();
  if (threadIdx.x == 0) g_mask_flag = found;
}

// ---------------- K1: QKV projection GEMM (4096x512 @ 512x512) ----------------
// sel 0 (q) / 1 (k): single-TF32 mma, output tf32-ROUNDED (makes QK^T exact).
// sel 2 (v): 3xTF32, full-precision output.
__global__ __launch_bounds__(256) void proj_kernel(
    const float* __restrict__ x, const float* __restrict__ W,
    const float* __restrict__ bias, const float* __restrict__ ct_key,
    const int* __restrict__ ctype, int sel)
{
  __shared__ float xs[64][33];
  __shared__ float ws[32][65];
  float* out = (sel == 0) ? g_q : (sel == 1) ? g_k : g_v;

  const int t = threadIdx.x, lane = t & 31, warp = t >> 5;
  const int wm = warp & 3, wn = warp >> 2;
  const int row0 = blockIdx.x * 64, col0 = blockIdx.y * 64;
  float acc[4][4] = {};

  for (int kt = 0; kt < 512; kt += 32) {
    {
      int r = t >> 2, cs = (t & 3) * 8;
      const float4* p = reinterpret_cast<const float4*>(&x[(size_t)(row0 + r) * 512 + kt + cs]);
      float4 v0 = p[0], v1 = p[1];
      xs[r][cs+0]=v0.x; xs[r][cs+1]=v0.y; xs[r][cs+2]=v0.z; xs[r][cs+3]=v0.w;
      xs[r][cs+4]=v1.x; xs[r][cs+5]=v1.y; xs[r][cs+6]=v1.z; xs[r][cs+7]=v1.w;
    }
    {
      int r = t >> 3, cs = (t & 7) * 8;
      const float4* p = reinterpret_cast<const float4*>(&W[(size_t)(kt + r) * 512 + col0 + cs]);
      float4 v0 = p[0], v1 = p[1];
      ws[r][cs+0]=v0.x; ws[r][cs+1]=v0.y; ws[r][cs+2]=v0.z; ws[r][cs+3]=v0.w;
      ws[r][cs+4]=v1.x; ws[r][cs+5]=v1.y; ws[r][cs+6]=v1.z; ws[r][cs+7]=v1.w;
    }
    __syncthreads();
    if (sel == 2) {
      #pragma unroll
      for (int kk = 0; kk < 4; kk++) {
        int ar = wm * 16 + (lane >> 2), ac = kk * 8 + (lane & 3);
        uint32_t a0h,a0l,a1h,a1l,a2h,a2l,a3h,a3l;
        split2(xs[ar][ac],   a0h,a0l); split2(xs[ar+8][ac],   a1h,a1l);
        split2(xs[ar][ac+4], a2h,a2l); split2(xs[ar+8][ac+4], a3h,a3l);
        #pragma unroll
        for (int nt = 0; nt < 4; nt++) {
          int bc = wn * 32 + nt * 8 + (lane >> 2);
          uint32_t b0h,b0l,b1h,b1l;
          split2(ws[kk*8 + (lane&3)][bc],     b0h,b0l);
          split2(ws[kk*8 + 4 + (lane&3)][bc], b1h,b1l);
          mma8_3x(acc[nt], a0h,a1h,a2h,a3h, a0l,a1l,a2l,a3l, b0h,b1h,b0l,b1l);
        }
      }
    } else {
      #pragma unroll
      for (int kk = 0; kk < 4; kk++) {
        int ar = wm * 16 + (lane >> 2), ac = kk * 8 + (lane & 3);
        uint32_t a0 = f2tf(xs[ar][ac]),   a1 = f2tf(xs[ar+8][ac]);
        uint32_t a2 = f2tf(xs[ar][ac+4]), a3 = f2tf(xs[ar+8][ac+4]);
        #pragma unroll
        for (int nt = 0; nt < 4; nt++) {
          int bc = wn * 32 + nt * 8 + (lane >> 2);
          uint32_t b0 = f2tf(ws[kk*8 + (lane&3)][bc]);
          uint32_t b1 = f2tf(ws[kk*8 + 4 + (lane&3)][bc]);
          mma8(acc[nt], a0, a1, a2, a3, b0, b1);
        }
      }
    }
    __syncthreads();
  }

  #pragma unroll
  for (int nt = 0; nt < 4; nt++) {
    #pragma unroll
    for (int q = 0; q < 4; q++) {
      int row = row0 + wm * 16 + (lane >> 2) + ((q >> 1) << 3);
      int col = col0 + wn * 32 + nt * 8 + 2 * (lane & 3) + (q & 1);
      int bidx = row >> 9, n = row & 511, h = col >> 6, d = col & 63;
      float v = acc[nt][q] + bias[col];
      if (sel == 1) v += ct_key[(size_t)ctype[bidx] * 512 + col];
      if (sel != 2) v = __uint_as_float(f2tf(v));  // tf32-round q,k
      out[(((size_t)bidx * H_ + h) * N_ + n) * D_ + d] = v;
    }
  }
}

// ---------------- K2: edge MLP (32 -> 16 -> 8) + ct bias + masks --------------
// 256 threads, one block = (b, i, 128 j's).
__global__ __launch_bounds__(256) void edge_kernel(
    const float* __restrict__ ef, const float* __restrict__ We1,
    const float* __restrict__ be1, const float* __restrict__ We2,
    const float* __restrict__ be2, const float* __restrict__ ct_bias,
    const int* __restrict__ ctype, const void* __restrict__ bm_raw,
    const void* __restrict__ pm_raw)
{
  __shared__ float efs[128][33];  // ef tile (j, e)
  __shared__ float h1s[128][17];  // hidden layer (j, c)
  __shared__ float ws1[32][17];   // We1 (e, c)
  __shared__ float ws2[16][9];    // We2 (c, h)

  const int t = threadIdx.x, lane = t & 31, warp = t >> 5;
  const int lin = blockIdx.x;
  const int jt = lin & 3, i = (lin >> 2) & 511, b = lin >> 11;
  const int j0 = jt * 128;

  const int mbyte = g_mask_flag;
  const uint32_t*      bm32 = (const uint32_t*)bm_raw;
  const unsigned char* bm8  = (const unsigned char*)bm_raw;
  const uint32_t*      pm32 = (const uint32_t*)pm_raw;
  const unsigned char* pm8  = (const unsigned char*)pm_raw;

  { // ef tile: 128 j x 32 e = 1024 float4
    const float4* p = reinterpret_cast<const float4*>(&ef[(((size_t)b * 512 + i) * 512 + j0) * 32]);
    #pragma unroll
    for (int rep = 0; rep < 4; rep++) {
      int l4 = rep * 256 + t;
      float4 v = p[l4];
      int j = l4 >> 3, c = (l4 & 7) * 4;
      efs[j][c]=v.x; efs[j][c+1]=v.y; efs[j][c+2]=v.z; efs[j][c+3]=v.w;
    }
  }
  if (t < 128) { // We1: 512 floats
    int l = t * 4;
    float4 v = *reinterpret_cast<const float4*>(&We1[l]);
    int r = l >> 4, c = l & 15;
    ws1[r][c]=v.x; ws1[r][c+1]=v.y; ws1[r][c+2]=v.z; ws1[r][c+3]=v.w;
  }
  if (t < 32) { // We2: 128 floats
    int l = t * 4;
    float4 v = *reinterpret_cast<const float4*>(&We2[l]);
    int r = l >> 3, c = l & 7;
    ws2[r][c]=v.x; ws2[r][c+1]=v.y; ws2[r][c+2]=v.z; ws2[r][c+3]=v.w;
  }
  __syncthreads();

  // layer 1: (128x32)@(32x16). warp owns 16 rows x 16 cols (2 n-tiles)
  float acc1[2][4] = {};
  #pragma unroll
  for (int kk = 0; kk < 4; kk++) {
    int ar = warp * 16 + (lane >> 2), ac = kk * 8 + (lane & 3);
    uint32_t a0 = f2tf(efs[ar][ac]),   a1 = f2tf(efs[ar+8][ac]);
    uint32_t a2 = f2tf(efs[ar][ac+4]), a3 = f2tf(efs[ar+8][ac+4]);
    #pragma unroll
    for (int nt = 0; nt < 2; nt++) {
      uint32_t b0 = f2tf(ws1[kk*8 + (lane&3)][nt*8 + (lane>>2)]);
      uint32_t b1 = f2tf(ws1[kk*8 + 4 + (lane&3)][nt*8 + (lane>>2)]);
      mma8(acc1[nt], a0, a1, a2, a3, b0, b1);
    }
  }

  // elu -> h1s (fp32)
  #pragma unroll
  for (int nt = 0; nt < 2; nt++)
    #pragma unroll
    for (int q = 0; q < 4; q++) {
      int row = warp * 16 + (lane >> 2) + ((q >> 1) << 3);
      int col = nt * 8 + 2 * (lane & 3) + (q & 1);
      float v = acc1[nt][q] + be1[col];
      h1s[row][col] = (v > 0.f) ? v : expm1f(v);
    }
  __syncthreads();

  // layer 2: (128x16)@(16x8)
  float acc2[4] = {};
  #pragma unroll
  for (int kk = 0; kk < 2; kk++) {
    int ar = warp * 16 + (lane >> 2), ac = kk * 8 + (lane & 3);
    uint32_t a0 = f2tf(h1s[ar][ac]),   a1 = f2tf(h1s[ar+8][ac]);
    uint32_t a2 = f2tf(h1s[ar][ac+4]), a3 = f2tf(h1s[ar+8][ac+4]);
    uint32_t b0 = f2tf(ws2[kk*8 + (lane&3)][lane>>2]);
    uint32_t b1 = f2tf(ws2[kk*8 + 4 + (lane&3)][lane>>2]);
    mma8(acc2, a0, a1, a2, a3, b0, b1);
  }

  const int ct = ctype[b];
  const bool pad_i = mbyte ? (pm8[b * 512 + i] != 0) : (pm32[b * 512 + i] != 0u);
  #pragma unroll
  for (int q = 0; q < 4; q++) {
    int row = warp * 16 + (lane >> 2) + ((q >> 1) << 3);
    int h = 2 * (lane & 3) + (q & 1);
    int j = j0 + row;
    size_t bij = ((size_t)b * 512 + i) * 512 + j;
    bool masked;
    if (mbyte)
      masked = pad_i || (bm8[bij] != 0) || (pm8[b * 512 + j] != 0);
    else
      masked = pad_i || (bm32[bij] != 0u) || (pm32[b * 512 + j] != 0u);
    float v = masked ? neginf() : (acc2[q] + be2[h] + ct_bias[ct * 8 + h]);
    g_att[(((size_t)b * H_ + h) * N_ + i) * N_ + j] = v;
  }
}

// ---------------- K3: attention ------------------------------------------------
// S = QK^T/8 + bias (single-TF32: q,k are tf32-rounded so the mma is exact),
// softmax, P@V (3xTF32). Q fragments hoisted; K/V tiles double-buffered.
__global__ __launch_bounds__(128) void attn_kernel()
{
  __shared__ float S[16][513];
  __shared__ float Qs[16][65];
  __shared__ float KVs[2][32][65];
  __shared__ float rmax[16], rinv[16];

  const int t = threadIdx.x, lane = t & 31, warp = t >> 5;
  const int bh = blockIdx.x;
  const int i0 = blockIdx.y * 16;

  const float* qb = g_q + (size_t)bh * N_ * D_;
  const float* kb = g_k + (size_t)bh * N_ * D_;
  const float* vb = g_v + (size_t)bh * N_ * D_;
  float* attb = g_att + (size_t)bh * N_ * N_;

  #pragma unroll
  for (int rep = 0; rep < 2; rep++) { // Q tile 16x64
    int l4 = rep * 128 + t;
    int r = l4 >> 4, c = (l4 & 15) * 4;
    float4 v = *reinterpret_cast<const float4*>(&qb[(size_t)(i0 + r) * 64 + c]);
    Qs[r][c]=v.x; Qs[r][c+1]=v.y; Qs[r][c+2]=v.z; Qs[r][c+3]=v.w;
  }
  __syncthreads();

  // hoist Q fragments (tf32-representable -> reinterpret bits, no cvt)
  uint32_t qf[8][4];
  #pragma unroll
  for (int kk = 0; kk < 8; kk++) {
    int ar = lane >> 2, ac = kk * 8 + (lane & 3);
    qf[kk][0] = __float_as_uint(Qs[ar][ac]);
    qf[kk][1] = __float_as_uint(Qs[ar+8][ac]);
    qf[kk][2] = __float_as_uint(Qs[ar][ac+4]);
    qf[kk][3] = __float_as_uint(Qs[ar+8][ac+4]);
  }

  // ---- S phase: 16 j-tiles of 32, double-buffered, 1 barrier per tile ----
  for (int jt = 0; jt < 16; jt++) {
    float (*buf)[65] = KVs[jt & 1];
    #pragma unroll
    for (int rep = 0; rep < 4; rep++) { // K tile 32x64
      int l4 = rep * 128 + t;
      int r = l4 >> 4, c = (l4 & 15) * 4;
      float4 v = *reinterpret_cast<const float4*>(&kb[(size_t)(jt * 32 + r) * 64 + c]);
      buf[r][c]=v.x; buf[r][c+1]=v.y; buf[r][c+2]=v.z; buf[r][c+3]=v.w;
    }
    __syncthreads();
    float sacc[4] = {};
    int br = warp * 8 + (lane >> 2);
    #pragma unroll
    for (int kk = 0; kk < 8; kk++) {
      int ac = kk * 8 + (lane & 3);
      uint32_t b0 = __float_as_uint(buf[br][ac]);
      uint32_t b1 = __float_as_uint(buf[br][ac+4]);
      mma8(sacc, qf[kk][0], qf[kk][1], qf[kk][2], qf[kk][3], b0, b1);
    }
    #pragma unroll
    for (int q = 0; q < 4; q++) {
      int r = (lane >> 2) + ((q >> 1) << 3);
      int j = jt * 32 + warp * 8 + 2 * (lane & 3) + (q & 1);
      S[r][j] = sacc[q] * 0.125f + attb[(size_t)(i0 + r) * 512 + j];
    }
  }
  __syncthreads();

  // ---- softmax stats: 8 threads per row ----
  {
    int r = t >> 3, sub = t & 7;
    float m = neginf();
    for (int j = sub; j < 512; j += 8) m = fmaxf(m, S[r][j]);
    #pragma unroll
    for (int o = 4; o; o >>= 1) m = fmaxf(m, __shfl_xor_sync(0xffffffffu, m, o));
    float s = 0.f;
    if (m != neginf())
      for (int j = sub; j < 512; j += 8) s += expf(S[r][j] - m);
    #pragma unroll
    for (int o = 4; o; o >>= 1) s += __shfl_xor_sync(0xffffffffu, s, o);
    if (sub == 0) { rmax[r] = m; rinv[r] = (m == neginf() || s == 0.f) ? 0.f : 1.f / s; }
  }
  __syncthreads();

  // ---- normalize, write probs, keep probs in S ----
  for (int idx = t; idx < 16 * 512; idx += 128) {
    int r = idx >> 9, j = idx & 511;
    float inv = rinv[r];
    float p = (inv == 0.f) ? 0.f : expf(S[r][j] - rmax[r]) * inv;
    S[r][j] = p;
    attb[(size_t)(i0 + r) * 512 + j] = p;
  }
  __syncthreads();

  // ---- AV phase: out(16x64) = P(16x512) @ V(512x64), 3xTF32 ----
  float oacc[2][4] = {};
  for (int jt = 0; jt < 16; jt++) {
    float (*buf)[65] = KVs[jt & 1];
    #pragma unroll
    for (int rep = 0; rep < 4; rep++) { // V tile 32x64
      int l4 = rep * 128 + t;
      int r = l4 >> 4, c = (l4 & 15) * 4;
      float4 v = *reinterpret_cast<const float4*>(&vb[(size_t)(jt * 32 + r) * 64 + c]);
      buf[r][c]=v.x; buf[r][c+1]=v.y; buf[r][c+2]=v.z; buf[r][c+3]=v.w;
    }
    __syncthreads();
    #pragma unroll
    for (int kk = 0; kk < 4; kk++) {
      int ar = lane >> 2, ac = jt * 32 + kk * 8 + (lane & 3);
      uint32_t a0h,a0l,a1h,a1l,a2h,a2l,a3h,a3l;
      split2(S[ar][ac],   a0h,a0l); split2(S[ar+8][ac],   a1h,a1l);
      split2(S[ar][ac+4], a2h,a2l); split2(S[ar+8][ac+4], a3h,a3l);
      #pragma unroll
      for (int nt = 0; nt < 2; nt++) {
        int bc = warp * 16 + nt * 8 + (lane >> 2);
        uint32_t b0h,b0l,b1h,b1l;
        split2(buf[kk*8 + (lane&3)][bc],     b0h,b0l);
        split2(buf[kk*8 + 4 + (lane&3)][bc], b1h,b1l);
        mma8_3x(oacc[nt], a0h,a1h,a2h,a3h, a0l,a1l,a2l,a3l, b0h,b1h,b0l,b1l);
      }
    }
  }
  float* ob = g_outh + (size_t)bh * N_ * D_;
  #pragma unroll
  for (int nt = 0; nt < 2; nt++)
    #pragma unroll
    for (int q = 0; q < 4; q++) {
      int r = (lane >> 2) + ((q >> 1) << 3);
      int d = warp * 16 + nt * 8 + 2 * (lane & 3) + (q & 1);
      ob[(size_t)(i0 + r) * 64 + d] = oacc[nt][q];
    }
}

// ---------------- K4: head mean of probs ---------------------------------------
__global__ __launch_bounds__(256) void mean_kernel(float* __restrict__ outm)
{
  int idx = blockIdx.x * 256 + threadIdx.x;
  int b = idx >> 18;
  int ij = idx & 262143;
  const float* base = g_att + (size_t)b * H_ * 262144 + ij;
  float s = 0.f;
  #pragma unroll
  for (int h = 0; h < 8; h++) s += base[(size_t)h * 262144];
  outm[idx] = s * 0.125f;
}

// ---------------- K5: output projection (gathers heads), 3xTF32 ---------------
__global__ __launch_bounds__(256) void outproj_kernel(
    const float* __restrict__ Wo, const float* __restrict__ bo,
    float* __restrict__ out)
{
  __shared__ float xs[64][33];
  __shared__ float ws[32][65];
  const int t = threadIdx.x, lane = t & 31, warp = t >> 5;
  const int wm = warp & 3, wn = warp >> 2;
  const int row0 = blockIdx.x * 64, col0 = blockIdx.y * 64;
  float acc[4][4] = {};

  for (int kt = 0; kt < 512; kt += 32) {
    {
      int r = t >> 2, cs = (t & 3) * 8;
      int row = row0 + r, b = row >> 9, n = row & 511;
      int col = kt + cs, h = col >> 6, d = col & 63;
      const float4* p = reinterpret_cast<const float4*>(
          &g_outh[(((size_t)b * H_ + h) * N_ + n) * D_ + d]);
      float4 v0 = p[0], v1 = p[1];
      xs[r][cs+0]=v0.x; xs[r][cs+1]=v0.y; xs[r][cs+2]=v0.z; xs[r][cs+3]=v0.w;
      xs[r][cs+4]=v1.x; xs[r][cs+5]=v1.y; xs[r][cs+6]=v1.z; xs[r][cs+7]=v1.w;
    }
    {
      int r = t >> 3, cs = (t & 7) * 8;
      const float4* p = reinterpret_cast<const float4*>(&Wo[(size_t)(kt + r) * 512 + col0 + cs]);
      float4 v0 = p[0], v1 = p[1];
      ws[r][cs+0]=v0.x; ws[r][cs+1]=v0.y; ws[r][cs+2]=v0.z; ws[r][cs+3]=v0.w;
      ws[r][cs+4]=v1.x; ws[r][cs+5]=v1.y; ws[r][cs+6]=v1.z; ws[r][cs+7]=v1.w;
    }
    __syncthreads();
    #pragma unroll
    for (int kk = 0; kk < 4; kk++) {
      int ar = wm * 16 + (lane >> 2), ac = kk * 8 + (lane & 3);
      uint32_t a0h,a0l,a1h,a1l,a2h,a2l,a3h,a3l;
      split2(xs[ar][ac],   a0h,a0l); split2(xs[ar+8][ac],   a1h,a1l);
      split2(xs[ar][ac+4], a2h,a2l); split2(xs[ar+8][ac+4], a3h,a3l);
      #pragma unroll
      for (int nt = 0; nt < 4; nt++) {
        int bc = wn * 32 + nt * 8 + (lane >> 2);
        uint32_t b0h,b0l,b1h,b1l;
        split2(ws[kk*8 + (lane&3)][bc],     b0h,b0l);
        split2(ws[kk*8 + 4 + (lane&3)][bc], b1h,b1l);
        mma8_3x(acc[nt], a0h,a1h,a2h,a3h, a0l,a1l,a2l,a3l, b0h,b1h,b0l,b1l);
      }
    }
    __syncthreads();
  }
  #pragma unroll
  for (int nt = 0; nt < 4; nt++)
    #pragma unroll
    for (int q = 0; q < 4; q++) {
      int row = row0 + wm * 16 + (lane >> 2) + ((q >> 1) << 3);
      int col = col0 + wn * 32 + nt * 8 + 2 * (lane & 3) + (q & 1);
      out[(size_t)row * 512 + col] = acc[nt][q] + bo[col];
    }
}

// ---------------- launch --------------------------------------------------------
extern "C" void kernel_launch(void* const* d_in, const int* in_sizes, int n_in,
                              void* d_out, int out_size)
{
  (void)in_sizes; (void)n_in; (void)out_size;
  const float* x   = (const float*)d_in[0];
  const int*   ct  = (const int*)d_in[1];
  const float* ef  = (const float*)d_in[2];
  const void*  bm  = d_in[3];
  const void*  pm  = d_in[4];
  const float* Wq  = (const float*)d_in[5];  const float* bq  = (const float*)d_in[6];
  const float* Wk  = (const float*)d_in[7];  const float* bk  = (const float*)d_in[8];
  const float* Wv  = (const float*)d_in[9];  const float* bv  = (const float*)d_in[10];
  const float* Wo  = (const float*)d_in[11]; const float* bo  = (const float*)d_in[12];
  const float* We1 = (const float*)d_in[13]; const float* be1 = (const float*)d_in[14];
  const float* We2 = (const float*)d_in[15]; const float* be2 = (const float*)d_in[16];
  const float* ctk = (const float*)d_in[17]; const float* ctb = (const float*)d_in[18];
  float* out = (float*)d_out;

  detect_mask_kernel<<<1, 256>>>((const uint32_t*)pm);

  dim3 gproj(64, 8);
  proj_kernel<<<gproj, 256>>>(x, Wq, bq, ctk, ct, 0);
  proj_kernel<<<gproj, 256>>>(x, Wk, bk, ctk, ct, 1);
  proj_kernel<<<gproj, 256>>>(x, Wv, bv, ctk, ct, 2);

  edge_kernel<<<B_ * N_ * (N_ / 128), 256>>>(ef, We1, be1, We2, be2, ctb, ct, bm, pm);

  attn_kernel<<<dim3(B_ * H_, N_ / 16), 128>>>();

  mean_kernel<<<(B_ * N_ * N_) / 256, 256>>>(out + (size_t)B_ * N_ * HID_);

  outproj_kernel<<<gproj, 256>>>(Wo, bo, out);
}

// round 14
// speedup vs baseline: 1.4245x; 1.3536x over previous
#include <cuda_runtime.h>
#include <cstdint>
#include <math.h>

// Problem constants
#define B_  8
#define N_  512
#define HID_ 512
#define H_  8
#define E_  32
#define D_  64

// ---------------- scratch (device globals; no runtime allocation) -------------
__device__ float g_q[B_*H_*N_*D_];          // (b,h,n,d) tf32-rounded  8 MB
__device__ float g_k[B_*H_*N_*D_];          // tf32-rounded            8 MB
__device__ float g_v[B_*H_*N_*D_];          // full fp32               8 MB
__device__ float g_att[(size_t)B_*H_*N_*N_];// bias -> probs, (b,h,i,j) 64 MB
__device__ float g_outh[B_*H_*N_*D_];       // attention output per head 8 MB
__device__ int   g_mask_flag;               // 0 = 4-byte words, 1 = packed bytes

// ---------------- helpers ------------------------------------------------------
__device__ __forceinline__ uint32_t f2tf(float f){
  uint32_t u; asm("cvt.rna.tf32.f32 %0, %1;" : "=r"(u) : "f"(f)); return u;
}
__device__ __forceinline__ void split2(float x, uint32_t& hi, uint32_t& lo){
  asm("cvt.rna.tf32.f32 %0, %1;" : "=r"(hi) : "f"(x));
  float r = x - __uint_as_float(hi);
  asm("cvt.rna.tf32.f32 %0, %1;" : "=r"(lo) : "f"(r));
}
__device__ __forceinline__ void mma8(float c[4],
    uint32_t a0,uint32_t a1,uint32_t a2,uint32_t a3,uint32_t b0,uint32_t b1){
  asm volatile("mma.sync.aligned.m16n8k8.row.col.f32.tf32.tf32.f32 "
    "{%0,%1,%2,%3}, {%4,%5,%6,%7}, {%8,%9}, {%0,%1,%2,%3};\n"
    : "+f"(c[0]),"+f"(c[1]),"+f"(c[2]),"+f"(c[3])
    : "r"(a0),"r"(a1),"r"(a2),"r"(a3),"r"(b0),"r"(b1));
}
__device__ __forceinline__ void mma8_3x(float c[4],
    uint32_t a0h,uint32_t a1h,uint32_t a2h,uint32_t a3h,
    uint32_t a0l,uint32_t a1l,uint32_t a2l,uint32_t a3l,
    uint32_t b0h,uint32_t b1h,uint32_t b0l,uint32_t b1l){
  mma8(c, a0h,a1h,a2h,a3h, b0l,b1l);
  mma8(c, a0l,a1l,a2l,a3l, b0h,b1h);
  mma8(c, a0h,a1h,a2h,a3h, b0h,b1h);
}
__device__ __forceinline__ float neginf(){ return __int_as_float(0xff800000u); }

// ---------------- K0: detect mask storage dtype --------------------------------
__global__ void detect_mask_kernel(const uint32_t* __restrict__ pm_words)
{
  __shared__ int found;
  if (threadIdx.x == 0) found = 0;
  __syncthreads();
  for (int i = threadIdx.x; i < 1024; i += blockDim.x) {
    uint32_t w = pm_words[i];
    if (w != 0u && w != 1u && w != 0x3F800000u) found = 1;
  }
  __syncthreads();
  if (threadIdx.x == 0) g_mask_flag = found;
}

// ---------------- K1: QKV projection GEMM (4096x512 @ 512x512) ----------------
// Conflict-free pitches: xs 36 (A-style), ws 72 (B-style). float4 staging.
__global__ __launch_bounds__(256) void proj_kernel(
    const float* __restrict__ x, const float* __restrict__ W,
    const float* __restrict__ bias, const float* __restrict__ ct_key,
    const int* __restrict__ ctype, int sel)
{
  __shared__ float xs[64][36];
  __shared__ float ws[32][72];
  float* out = (sel == 0) ? g_q : (sel == 1) ? g_k : g_v;

  const int t = threadIdx.x, lane = t & 31, warp = t >> 5;
  const int wm = warp & 3, wn = warp >> 2;
  const int row0 = blockIdx.x * 64, col0 = blockIdx.y * 64;
  float acc[4][4] = {};

  for (int kt = 0; kt < 512; kt += 32) {
    {
      int r = t >> 2, cs = (t & 3) * 8;
      const float4* p = reinterpret_cast<const float4*>(&x[(size_t)(row0 + r) * 512 + kt + cs]);
      *reinterpret_cast<float4*>(&xs[r][cs])     = p[0];
      *reinterpret_cast<float4*>(&xs[r][cs + 4]) = p[1];
    }
    {
      int r = t >> 3, cs = (t & 7) * 8;
      const float4* p = reinterpret_cast<const float4*>(&W[(size_t)(kt + r) * 512 + col0 + cs]);
      *reinterpret_cast<float4*>(&ws[r][cs])     = p[0];
      *reinterpret_cast<float4*>(&ws[r][cs + 4]) = p[1];
    }
    __syncthreads();
    if (sel == 2) {
      #pragma unroll
      for (int kk = 0; kk < 4; kk++) {
        int ar = wm * 16 + (lane >> 2), ac = kk * 8 + (lane & 3);
        uint32_t a0h,a0l,a1h,a1l,a2h,a2l,a3h,a3l;
        split2(xs[ar][ac],   a0h,a0l); split2(xs[ar+8][ac],   a1h,a1l);
        split2(xs[ar][ac+4], a2h,a2l); split2(xs[ar+8][ac+4], a3h,a3l);
        #pragma unroll
        for (int nt = 0; nt < 4; nt++) {
          int bc = wn * 32 + nt * 8 + (lane >> 2);
          uint32_t b0h,b0l,b1h,b1l;
          split2(ws[kk*8 + (lane&3)][bc],     b0h,b0l);
          split2(ws[kk*8 + 4 + (lane&3)][bc], b1h,b1l);
          mma8_3x(acc[nt], a0h,a1h,a2h,a3h, a0l,a1l,a2l,a3l, b0h,b1h,b0l,b1l);
        }
      }
    } else {
      #pragma unroll
      for (int kk = 0; kk < 4; kk++) {
        int ar = wm * 16 + (lane >> 2), ac = kk * 8 + (lane & 3);
        uint32_t a0 = f2tf(xs[ar][ac]),   a1 = f2tf(xs[ar+8][ac]);
        uint32_t a2 = f2tf(xs[ar][ac+4]), a3 = f2tf(xs[ar+8][ac+4]);
        #pragma unroll
        for (int nt = 0; nt < 4; nt++) {
          int bc = wn * 32 + nt * 8 + (lane >> 2);
          uint32_t b0 = f2tf(ws[kk*8 + (lane&3)][bc]);
          uint32_t b1 = f2tf(ws[kk*8 + 4 + (lane&3)][bc]);
          mma8(acc[nt], a0, a1, a2, a3, b0, b1);
        }
      }
    }
    __syncthreads();
  }

  #pragma unroll
  for (int nt = 0; nt < 4; nt++) {
    #pragma unroll
    for (int q = 0; q < 4; q++) {
      int row = row0 + wm * 16 + (lane >> 2) + ((q >> 1) << 3);
      int col = col0 + wn * 32 + nt * 8 + 2 * (lane & 3) + (q & 1);
      int bidx = row >> 9, n = row & 511, h = col >> 6, d = col & 63;
      float v = acc[nt][q] + bias[col];
      if (sel == 1) v += ct_key[(size_t)ctype[bidx] * 512 + col];
      if (sel != 2) v = __uint_as_float(f2tf(v));  // tf32-round q,k
      out[(((size_t)bidx * H_ + h) * N_ + n) * D_ + d] = v;
    }
  }
}

// ---------------- K2: edge MLP (32 -> 16 -> 8) + ct bias + masks --------------
// 256 threads, one block = (b, i, 128 j's). Conflict-free pitches.
__global__ __launch_bounds__(256) void edge_kernel(
    const float* __restrict__ ef, const float* __restrict__ We1,
    const float* __restrict__ be1, const float* __restrict__ We2,
    const float* __restrict__ be2, const float* __restrict__ ct_bias,
    const int* __restrict__ ctype, const void* __restrict__ bm_raw,
    const void* __restrict__ pm_raw)
{
  __shared__ float efs[128][36];  // A-style pitch
  __shared__ float h1s[128][20];  // A-style (20r+c distinct)
  __shared__ float ws1[32][24];   // B-style (24r+c distinct)
  __shared__ float ws2[16][8];    // B-style (8r+c distinct)

  const int t = threadIdx.x, lane = t & 31, warp = t >> 5;
  const int lin = blockIdx.x;
  const int jt = lin & 3, i = (lin >> 2) & 511, b = lin >> 11;
  const int j0 = jt * 128;

  const int mbyte = g_mask_flag;
  const uint32_t*      bm32 = (const uint32_t*)bm_raw;
  const unsigned char* bm8  = (const unsigned char*)bm_raw;
  const uint32_t*      pm32 = (const uint32_t*)pm_raw;
  const unsigned char* pm8  = (const unsigned char*)pm_raw;

  { // ef tile: 128 j x 32 e = 1024 float4
    const float4* p = reinterpret_cast<const float4*>(&ef[(((size_t)b * 512 + i) * 512 + j0) * 32]);
    #pragma unroll
    for (int rep = 0; rep < 4; rep++) {
      int l4 = rep * 256 + t;
      float4 v = p[l4];
      int j = l4 >> 3, c = (l4 & 7) * 4;
      *reinterpret_cast<float4*>(&efs[j][c]) = v;
    }
  }
  if (t < 128) { // We1: 512 floats
    int l = t * 4;
    float4 v = *reinterpret_cast<const float4*>(&We1[l]);
    *reinterpret_cast<float4*>(&ws1[l >> 4][l & 15]) = v;
  }
  if (t < 32) { // We2: 128 floats
    int l = t * 4;
    float4 v = *reinterpret_cast<const float4*>(&We2[l]);
    *reinterpret_cast<float4*>(&ws2[l >> 3][l & 7]) = v;
  }
  __syncthreads();

  // layer 1: (128x32)@(32x16). warp owns 16 rows x 16 cols (2 n-tiles)
  float acc1[2][4] = {};
  #pragma unroll
  for (int kk = 0; kk < 4; kk++) {
    int ar = warp * 16 + (lane >> 2), ac = kk * 8 + (lane & 3);
    uint32_t a0 = f2tf(efs[ar][ac]),   a1 = f2tf(efs[ar+8][ac]);
    uint32_t a2 = f2tf(efs[ar][ac+4]), a3 = f2tf(efs[ar+8][ac+4]);
    #pragma unroll
    for (int nt = 0; nt < 2; nt++) {
      uint32_t b0 = f2tf(ws1[kk*8 + (lane&3)][nt*8 + (lane>>2)]);
      uint32_t b1 = f2tf(ws1[kk*8 + 4 + (lane&3)][nt*8 + (lane>>2)]);
      mma8(acc1[nt], a0, a1, a2, a3, b0, b1);
    }
  }

  // elu -> h1s (fp32)
  #pragma unroll
  for (int nt = 0; nt < 2; nt++)
    #pragma unroll
    for (int q = 0; q < 4; q++) {
      int row = warp * 16 + (lane >> 2) + ((q >> 1) << 3);
      int col = nt * 8 + 2 * (lane & 3) + (q & 1);
      float v = acc1[nt][q] + be1[col];
      h1s[row][col] = (v > 0.f) ? v : expm1f(v);
    }
  __syncthreads();

  // layer 2: (128x16)@(16x8)
  float acc2[4] = {};
  #pragma unroll
  for (int kk = 0; kk < 2; kk++) {
    int ar = warp * 16 + (lane >> 2), ac = kk * 8 + (lane & 3);
    uint32_t a0 = f2tf(h1s[ar][ac]),   a1 = f2tf(h1s[ar+8][ac]);
    uint32_t a2 = f2tf(h1s[ar][ac+4]), a3 = f2tf(h1s[ar+8][ac+4]);
    uint32_t b0 = f2tf(ws2[kk*8 + (lane&3)][lane>>2]);
    uint32_t b1 = f2tf(ws2[kk*8 + 4 + (lane&3)][lane>>2]);
    mma8(acc2, a0, a1, a2, a3, b0, b1);
  }

  const int ct = ctype[b];
  const bool pad_i = mbyte ? (pm8[b * 512 + i] != 0) : (pm32[b * 512 + i] != 0u);
  #pragma unroll
  for (int q = 0; q < 4; q++) {
    int row = warp * 16 + (lane >> 2) + ((q >> 1) << 3);
    int h = 2 * (lane & 3) + (q & 1);
    int j = j0 + row;
    size_t bij = ((size_t)b * 512 + i) * 512 + j;
    bool masked;
    if (mbyte)
      masked = pad_i || (bm8[bij] != 0) || (pm8[b * 512 + j] != 0);
    else
      masked = pad_i || (bm32[bij] != 0u) || (pm32[b * 512 + j] != 0u);
    float v = masked ? neginf() : (acc2[q] + be2[h] + ct_bias[ct * 8 + h]);
    g_att[(((size_t)b * H_ + h) * N_ + i) * N_ + j] = v;
  }
}

// ---------------- K3: attention ------------------------------------------------
// S = QK^T/8 + bias (single-TF32 exact on tf32-rounded q,k), softmax, P@V (3x).
// Conflict-free pitches: Qs/S/K A-style (68/516/68), V B-style (72).
__global__ __launch_bounds__(128) void attn_kernel()
{
  __shared__ float S[16][516];
  __shared__ float Qs[16][68];
  __shared__ float Ks[32][68];
  __shared__ float Vs[32][72];
  __shared__ float rmax[16], rinv[16];

  const int t = threadIdx.x, lane = t & 31, warp = t >> 5;
  const int bh = blockIdx.x;
  const int i0 = blockIdx.y * 16;

  const float* qb = g_q + (size_t)bh * N_ * D_;
  const float* kb = g_k + (size_t)bh * N_ * D_;
  const float* vb = g_v + (size_t)bh * N_ * D_;
  float* attb = g_att + (size_t)bh * N_ * N_;

  #pragma unroll
  for (int rep = 0; rep < 2; rep++) { // Q tile 16x64
    int l4 = rep * 128 + t;
    int r = l4 >> 4, c = (l4 & 15) * 4;
    *reinterpret_cast<float4*>(&Qs[r][c]) =
        *reinterpret_cast<const float4*>(&qb[(size_t)(i0 + r) * 64 + c]);
  }
  __syncthreads();

  // hoist Q fragments (tf32-representable -> reinterpret bits)
  uint32_t qf[8][4];
  #pragma unroll
  for (int kk = 0; kk < 8; kk++) {
    int ar = lane >> 2, ac = kk * 8 + (lane & 3);
    qf[kk][0] = __float_as_uint(Qs[ar][ac]);
    qf[kk][1] = __float_as_uint(Qs[ar+8][ac]);
    qf[kk][2] = __float_as_uint(Qs[ar][ac+4]);
    qf[kk][3] = __float_as_uint(Qs[ar+8][ac+4]);
  }

  // ---- S phase: 16 j-tiles of 32 ----
  for (int jt = 0; jt < 16; jt++) {
    __syncthreads();
    #pragma unroll
    for (int rep = 0; rep < 4; rep++) { // K tile 32x64
      int l4 = rep * 128 + t;
      int r = l4 >> 4, c = (l4 & 15) * 4;
      *reinterpret_cast<float4*>(&Ks[r][c]) =
          *reinterpret_cast<const float4*>(&kb[(size_t)(jt * 32 + r) * 64 + c]);
    }
    __syncthreads();
    float sacc[4] = {};
    int br = warp * 8 + (lane >> 2);
    #pragma unroll
    for (int kk = 0; kk < 8; kk++) {
      int ac = kk * 8 + (lane & 3);
      uint32_t b0 = __float_as_uint(Ks[br][ac]);
      uint32_t b1 = __float_as_uint(Ks[br][ac+4]);
      mma8(sacc, qf[kk][0], qf[kk][1], qf[kk][2], qf[kk][3], b0, b1);
    }
    #pragma unroll
    for (int q = 0; q < 4; q++) {
      int r = (lane >> 2) + ((q >> 1) << 3);
      int j = jt * 32 + warp * 8 + 2 * (lane & 3) + (q & 1);
      S[r][j] = sacc[q] * 0.125f + attb[(size_t)(i0 + r) * 512 + j];
    }
  }
  __syncthreads();

  // ---- softmax stats: 8 threads per row ----
  {
    int r = t >> 3, sub = t & 7;
    float m = neginf();
    for (int j = sub; j < 512; j += 8) m = fmaxf(m, S[r][j]);
    #pragma unroll
    for (int o = 4; o; o >>= 1) m = fmaxf(m, __shfl_xor_sync(0xffffffffu, m, o));
    float s = 0.f;
    if (m != neginf())
      for (int j = sub; j < 512; j += 8) s += expf(S[r][j] - m);
    #pragma unroll
    for (int o = 4; o; o >>= 1) s += __shfl_xor_sync(0xffffffffu, s, o);
    if (sub == 0) { rmax[r] = m; rinv[r] = (m == neginf() || s == 0.f) ? 0.f : 1.f / s; }
  }
  __syncthreads();

  // ---- normalize, write probs, keep probs in S ----
  for (int idx = t; idx < 16 * 512; idx += 128) {
    int r = idx >> 9, j = idx & 511;
    float inv = rinv[r];
    float p = (inv == 0.f) ? 0.f : expf(S[r][j] - rmax[r]) * inv;
    S[r][j] = p;
    attb[(size_t)(i0 + r) * 512 + j] = p;
  }

  // ---- AV phase: out(16x64) = P(16x512) @ V(512x64), 3xTF32 ----
  float oacc[2][4] = {};
  for (int jt = 0; jt < 16; jt++) {
    __syncthreads();
    #pragma unroll
    for (int rep = 0; rep < 4; rep++) { // V tile 32x64
      int l4 = rep * 128 + t;
      int r = l4 >> 4, c = (l4 & 15) * 4;
      *reinterpret_cast<float4*>(&Vs[r][c]) =
          *reinterpret_cast<const float4*>(&vb[(size_t)(jt * 32 + r) * 64 + c]);
    }
    __syncthreads();
    #pragma unroll
    for (int kk = 0; kk < 4; kk++) {
      int ar = lane >> 2, ac = jt * 32 + kk * 8 + (lane & 3);
      uint32_t a0h,a0l,a1h,a1l,a2h,a2l,a3h,a3l;
      split2(S[ar][ac],   a0h,a0l); split2(S[ar+8][ac],   a1h,a1l);
      split2(S[ar][ac+4], a2h,a2l); split2(S[ar+8][ac+4], a3h,a3l);
      #pragma unroll
      for (int nt = 0; nt < 2; nt++) {
        int bc = warp * 16 + nt * 8 + (lane >> 2);
        uint32_t b0h,b0l,b1h,b1l;
        split2(Vs[kk*8 + (lane&3)][bc],     b0h,b0l);
        split2(Vs[kk*8 + 4 + (lane&3)][bc], b1h,b1l);
        mma8_3x(oacc[nt], a0h,a1h,a2h,a3h, a0l,a1l,a2l,a3l, b0h,b1h,b0l,b1l);
      }
    }
  }
  float* ob = g_outh + (size_t)bh * N_ * D_;
  #pragma unroll
  for (int nt = 0; nt < 2; nt++)
    #pragma unroll
    for (int q = 0; q < 4; q++) {
      int r = (lane >> 2) + ((q >> 1) << 3);
      int d = warp * 16 + nt * 8 + 2 * (lane & 3) + (q & 1);
      ob[(size_t)(i0 + r) * 64 + d] = oacc[nt][q];
    }
}

// ---------------- K4: head mean of probs ---------------------------------------
__global__ __launch_bounds__(256) void mean_kernel(float* __restrict__ outm)
{
  int idx = blockIdx.x * 256 + threadIdx.x;
  int b = idx >> 18;
  int ij = idx & 262143;
  const float* base = g_att + (size_t)b * H_ * 262144 + ij;
  float s = 0.f;
  #pragma unroll
  for (int h = 0; h < 8; h++) s += base[(size_t)h * 262144];
  outm[idx] = s * 0.125f;
}

// ---------------- K5: output projection (gathers heads), 3xTF32 ---------------
__global__ __launch_bounds__(256) void outproj_kernel(
    const float* __restrict__ Wo, const float* __restrict__ bo,
    float* __restrict__ out)
{
  __shared__ float xs[64][36];
  __shared__ float ws[32][72];
  const int t = threadIdx.x, lane = t & 31, warp = t >> 5;
  const int wm = warp & 3, wn = warp >> 2;
  const int row0 = blockIdx.x * 64, col0 = blockIdx.y * 64;
  float acc[4][4] = {};

  for (int kt = 0; kt < 512; kt += 32) {
    {
      int r = t >> 2, cs = (t & 3) * 8;
      int row = row0 + r, b = row >> 9, n = row & 511;
      int col = kt + cs, h = col >> 6, d = col & 63;
      const float4* p = reinterpret_cast<const float4*>(
          &g_outh[(((size_t)b * H_ + h) * N_ + n) * D_ + d]);
      *reinterpret_cast<float4*>(&xs[r][cs])     = p[0];
      *reinterpret_cast<float4*>(&xs[r][cs + 4]) = p[1];
    }
    {
      int r = t >> 3, cs = (t & 7) * 8;
      const float4* p = reinterpret_cast<const float4*>(&Wo[(size_t)(kt + r) * 512 + col0 + cs]);
      *reinterpret_cast<float4*>(&ws[r][cs])     = p[0];
      *reinterpret_cast<float4*>(&ws[r][cs + 4]) = p[1];
    }
    __syncthreads();
    #pragma unroll
    for (int kk = 0; kk < 4; kk++) {
      int ar = wm * 16 + (lane >> 2), ac = kk * 8 + (lane & 3);
      uint32_t a0h,a0l,a1h,a1l,a2h,a2l,a3h,a3l;
      split2(xs[ar][ac],   a0h,a0l); split2(xs[ar+8][ac],   a1h,a1l);
      split2(xs[ar][ac+4], a2h,a2l); split2(xs[ar+8][ac+4], a3h,a3l);
      #pragma unroll
      for (int nt = 0; nt < 4; nt++) {
        int bc = wn * 32 + nt * 8 + (lane >> 2);
        uint32_t b0h,b0l,b1h,b1l;
        split2(ws[kk*8 + (lane&3)][bc],     b0h,b0l);
        split2(ws[kk*8 + 4 + (lane&3)][bc], b1h,b1l);
        mma8_3x(acc[nt], a0h,a1h,a2h,a3h, a0l,a1l,a2l,a3l, b0h,b1h,b0l,b1l);
      }
    }
    __syncthreads();
  }
  #pragma unroll
  for (int nt = 0; nt < 4; nt++)
    #pragma unroll
    for (int q = 0; q < 4; q++) {
      int row = row0 + wm * 16 + (lane >> 2) + ((q >> 1) << 3);
      int col = col0 + wn * 32 + nt * 8 + 2 * (lane & 3) + (q & 1);
      out[(size_t)row * 512 + col] = acc[nt][q] + bo[col];
    }
}

// ---------------- launch --------------------------------------------------------
// R14 = R13 resubmitted verbatim: R13 died at container acquisition
// ("GB300 container failed twice"); the conflict-free-pitch experiment has
// not yet run on hardware.
extern "C" void kernel_launch(void* const* d_in, const int* in_sizes, int n_in,
                              void* d_out, int out_size)
{
  (void)in_sizes; (void)n_in; (void)out_size;
  const float* x   = (const float*)d_in[0];
  const int*   ct  = (const int*)d_in[1];
  const float* ef  = (const float*)d_in[2];
  const void*  bm  = d_in[3];
  const void*  pm  = d_in[4];
  const float* Wq  = (const float*)d_in[5];  const float* bq  = (const float*)d_in[6];
  const float* Wk  = (const float*)d_in[7];  const float* bk  = (const float*)d_in[8];
  const float* Wv  = (const float*)d_in[9];  const float* bv  = (const float*)d_in[10];
  const float* Wo  = (const float*)d_in[11]; const float* bo  = (const float*)d_in[12];
  const float* We1 = (const float*)d_in[13]; const float* be1 = (const float*)d_in[14];
  const float* We2 = (const float*)d_in[15]; const float* be2 = (const float*)d_in[16];
  const float* ctk = (const float*)d_in[17]; const float* ctb = (const float*)d_in[18];
  float* out = (float*)d_out;

  detect_mask_kernel<<<1, 256>>>((const uint32_t*)pm);

  dim3 gproj(64, 8);
  proj_kernel<<<gproj, 256>>>(x, Wq, bq, ctk, ct, 0);
  proj_kernel<<<gproj, 256>>>(x, Wk, bk, ctk, ct, 1);
  proj_kernel<<<gproj, 256>>>(x, Wv, bv, ctk, ct, 2);

  edge_kernel<<<B_ * N_ * (N_ / 128), 256>>>(ef, We1, be1, We2, be2, ctb, ct, bm, pm);

  attn_kernel<<<dim3(B_ * H_, N_ / 16), 128>>>();

  mean_kernel<<<(B_ * N_ * N_) / 256, 256>>>(out + (size_t)B_ * N_ * HID_);

  outproj_kernel<<<gproj, 256>>>(Wo, bo, out);
}